// round 8
// baseline (speedup 1.0000x reference)
#include <cuda_runtime.h>

// CrossAttention collapses: K/V are one visual_features vector broadcast over
// all T keys; softmax over identical logits is uniform, so y == v everywhere:
//   out[b,t,:] = ((vf[b] @ Wv + bv) @ Wp + bp)   broadcast over t.
// x / Wq / bq / Wk / bk are mathematically dead.
//
// R3: split-K (63->15.4us). R5: persistent kernel regressed (grid barriers
// cost more than graph-node gaps). R6/R7: 3 kernels, no barriers; final
// split-K reduce folded into the broadcast kernel. (R6 bench was an infra
// failure; this re-runs that design.)

#define CDIM  1024
#define BDIM  4
#define TDIM  1024

// K1: vf @ Wv partials
#define KS1   32
#define ROWS1 (CDIM / KS1)    // 32
// K2: vv @ Wp partials (fewer chunks so K3's fold-in reduce stays cheap)
#define KS2   16
#define ROWS2 (CDIM / KS2)    // 64
#define JT    128             // threads per proj block
#define JSPAN (JT * 4)        // 512 columns per block
#define JBLK  (CDIM / JSPAN)  // 2
// K3: broadcast
#define TT    8               // t-rows per block

__device__ float g_pvv[KS1][BDIM][CDIM];  // partials of vf @ Wv
__device__ float g_pr [KS2][BDIM][CDIM];  // partials of vv @ Wp

// ---------------------------------------------------------------------------
// K1: g_pvv[k][b][j] = sum_{i in chunk k} vf[b,i] * Wv[i,j]
// grid (JBLK, BDIM, KS1), 128 threads.
__global__ __launch_bounds__(JT) void vv_partial_kernel(
    const float* __restrict__ vf, const float* __restrict__ Wv)
{
    const int jx = blockIdx.x, b = blockIdx.y, k = blockIdx.z;
    const int j0 = jx * JSPAN + threadIdx.x * 4;

    __shared__ float s_in[ROWS1];
    if (threadIdx.x < ROWS1)
        s_in[threadIdx.x] = vf[b * CDIM + k * ROWS1 + threadIdx.x];
    __syncthreads();

    float4 acc = make_float4(0.f, 0.f, 0.f, 0.f);
    #pragma unroll
    for (int i = 0; i < ROWS1; ++i) {
        const float4 w = __ldg((const float4*)&Wv[(k * ROWS1 + i) * CDIM + j0]);
        const float s = s_in[i];
        acc.x += s * w.x; acc.y += s * w.y; acc.z += s * w.z; acc.w += s * w.w;
    }
    *(float4*)&g_pvv[k][b][j0] = acc;
}

// ---------------------------------------------------------------------------
// K2: reduce the needed vv slice (64 values x 32 partials + bv) in shared,
// then g_pr[k][b][j] = sum_{i in chunk k} vv[i] * Wp[i,j].
// grid (JBLK, BDIM, KS2), 128 threads.
__global__ __launch_bounds__(JT) void r_partial_kernel(
    const float* __restrict__ bv, const float* __restrict__ Wp)
{
    const int jx = blockIdx.x, b = blockIdx.y, k = blockIdx.z;
    const int j0 = jx * JSPAN + threadIdx.x * 4;

    __shared__ float s_red[2][ROWS2];
    __shared__ float s_in[ROWS2];

    {
        const int i  = threadIdx.x & (ROWS2 - 1);  // 0..63
        const int kg = threadIdx.x >> 6;           // 0..1, 16 partials each
        float s = 0.f;
        #pragma unroll
        for (int kk = kg * 16; kk < kg * 16 + 16; ++kk)
            s += g_pvv[kk][b][k * ROWS2 + i];
        s_red[kg][i] = s;
    }
    __syncthreads();
    if (threadIdx.x < ROWS2)
        s_in[threadIdx.x] = s_red[0][threadIdx.x] + s_red[1][threadIdx.x]
                          + bv[k * ROWS2 + threadIdx.x];
    __syncthreads();

    float4 acc = make_float4(0.f, 0.f, 0.f, 0.f);
    #pragma unroll
    for (int i = 0; i < ROWS2; ++i) {
        const float4 w = __ldg((const float4*)&Wp[(k * ROWS2 + i) * CDIM + j0]);
        const float s = s_in[i];
        acc.x += s * w.x; acc.y += s * w.y; acc.z += s * w.z; acc.w += s * w.w;
    }
    *(float4*)&g_pr[k][b][j0] = acc;
}

// ---------------------------------------------------------------------------
// K3: fused final-reduce + broadcast. Each thread owns one float4 column:
//   r4 = bp[j0..3] + sum_{kk<16} g_pr[kk][b][j0..3]   (16 independent LDGs)
// then stores r4 to TT consecutive t rows (independent STG.128).
// grid (TDIM/TT, BDIM) = (128, 4), 256 threads.
__global__ __launch_bounds__(256) void rb_kernel(
    const float* __restrict__ bp, float4* __restrict__ out)
{
    const int tid = threadIdx.x;           // 0..255 == column/4
    const int b   = blockIdx.y;
    const int t0  = blockIdx.x * TT;
    const int j0  = tid * 4;

    float4 acc = __ldg((const float4*)&bp[j0]);
    #pragma unroll
    for (int kk = 0; kk < KS2; ++kk) {
        const float4 p = __ldg((const float4*)&g_pr[kk][b][j0]);
        acc.x += p.x; acc.y += p.y; acc.z += p.z; acc.w += p.w;
    }

    float4* __restrict__ p = out + (size_t)(b * TDIM + t0) * (CDIM / 4) + tid;
    #pragma unroll
    for (int t = 0; t < TT; ++t)
        p[t * (CDIM / 4)] = acc;
}

extern "C" void kernel_launch(void* const* d_in, const int* in_sizes, int n_in,
                              void* d_out, int out_size)
{
    (void)in_sizes; (void)n_in; (void)out_size;
    const float* vf = (const float*)d_in[1];
    const float* Wv = (const float*)d_in[6];
    const float* bv = (const float*)d_in[7];
    const float* Wp = (const float*)d_in[8];
    const float* bp = (const float*)d_in[9];

    dim3 g1(JBLK, BDIM, KS1);                 // 2 x 4 x 32 = 256 blocks
    vv_partial_kernel<<<g1, JT>>>(vf, Wv);

    dim3 g2(JBLK, BDIM, KS2);                 // 2 x 4 x 16 = 128 blocks
    r_partial_kernel<<<g2, JT>>>(bv, Wp);

    dim3 g3(TDIM / TT, BDIM);                 // 128 x 4 = 512 blocks
    rb_kernel<<<g3, 256>>>(bp, (float4*)d_out);
}